// round 14
// baseline (speedup 1.0000x reference)
#include <cuda_runtime.h>
#include <cuda_bf16.h>
#include <math.h>

// Fixed problem shape (from reference): B=128, S=2048, E=512, H=512.
#define MAX_B 128
#define MAX_S 2048
#define MAX_E 512
#define MAX_H 512
#define SPLITK 8
#define SETUP_BLOCKS 128
#define SCORE_BLOCKS 1024          // (S/256) * B
#define GRID_TOTAL (SETUP_BLOCKS + SCORE_BLOCKS)

__device__ float g_c[MAX_B];                        // c[b] = q[b].bk
__device__ float g_sum[MAX_B];                      // row sums of exp
__device__ unsigned g_cnt[MAX_B];                   // per-batch completion count
__device__ unsigned g_bar;                          // setup-internal barrier (monotonic)
__device__ unsigned g_setup_done;                   // setup completion count (monotonic)
__device__ unsigned g_launch_cnt;                   // blocks retired, ever (monotonic)
__device__ float g_part[SPLITK * MAX_B * MAX_H];    // q split-K partials
__device__ float g_part2[SPLITK * MAX_B * MAX_E];   // v split-K partials

// ---------------------------------------------------------------------------
// One 64x64 single-round split-K GEMM tile (device function).
// TRANSB=1: C = A @ Bm^T  (Bm [N,K] row-major).
// TRANSB=0/APART=1: A is a SPLITK-partial array; partials summed (+abias)
//           during the A load; bx==0 blocks accumulate c[m] += q[m,:].cw
//           into g_c via atomicAdd (tid<64).
// ---------------------------------------------------------------------------
template <int TRANSB, int APART>
__device__ __forceinline__ void gemm_tile(
    const float* __restrict__ A, const float* __restrict__ abias,
    const float* __restrict__ Bm, const float* __restrict__ cw,
    float* __restrict__ Cpart, int M, int N, int K,
    int bx, int by, int bz,
    float (*As)[68], float (*Bs)[68])
{
    int tid = threadIdx.x;
    int m0 = by * 64;
    int n0 = bx * 64;
    int kbeg = bz * 64;

#pragma unroll
    for (int t = 0; t < 4; t++) {
        int idx = tid + t * 256;
        int r = idx >> 4;
        int kq = (idx & 15) * 4;
        size_t off = (size_t)(m0 + r) * K + kbeg + kq;
        float4 a;
        if (APART) {
            int MK = M * K;
            float4 s = *(const float4*)&abias[kbeg + kq];
#pragma unroll
            for (int p = 0; p < SPLITK; p++) {
                float4 pp = *(const float4*)&A[(size_t)p * MK + off];
                s.x += pp.x; s.y += pp.y; s.z += pp.z; s.w += pp.w;
            }
            a = s;
        } else {
            a = *(const float4*)&A[off];
        }
        *(float4*)&As[r][kq] = a;
    }

    if (TRANSB) {
#pragma unroll
        for (int t = 0; t < 4; t++) {
            int idx = tid + t * 256;
            int n = idx >> 4;
            int kq = (idx & 15) * 4;
            float4 v = *(const float4*)&Bm[(size_t)(n0 + n) * K + kbeg + kq];
            Bs[kq][n] = v.x; Bs[kq + 1][n] = v.y; Bs[kq + 2][n] = v.z; Bs[kq + 3][n] = v.w;
        }
    } else {
#pragma unroll
        for (int t = 0; t < 4; t++) {
            int idx = tid + t * 256;
            int kk = idx >> 4;
            int nq = (idx & 15) * 4;
            *(float4*)&Bs[kk][nq] = *(const float4*)&Bm[(size_t)(kbeg + kk) * N + n0 + nq];
        }
    }
    __syncthreads();

    int tx = tid & 15;
    int ty = tid >> 4;
    float acc[4][4] = {};
#pragma unroll
    for (int kk = 0; kk < 64; kk++) {
        float a0 = As[ty * 4][kk];
        float a1 = As[ty * 4 + 1][kk];
        float a2 = As[ty * 4 + 2][kk];
        float a3 = As[ty * 4 + 3][kk];
        float4 bv = *(const float4*)&Bs[kk][tx * 4];
        acc[0][0] += a0 * bv.x; acc[0][1] += a0 * bv.y; acc[0][2] += a0 * bv.z; acc[0][3] += a0 * bv.w;
        acc[1][0] += a1 * bv.x; acc[1][1] += a1 * bv.y; acc[1][2] += a1 * bv.z; acc[1][3] += a1 * bv.w;
        acc[2][0] += a2 * bv.x; acc[2][1] += a2 * bv.y; acc[2][2] += a2 * bv.z; acc[2][3] += a2 * bv.w;
        acc[3][0] += a3 * bv.x; acc[3][1] += a3 * bv.y; acc[3][2] += a3 * bv.z; acc[3][3] += a3 * bv.w;
    }

#pragma unroll
    for (int r = 0; r < 4; r++) {
        float4 o = make_float4(acc[r][0], acc[r][1], acc[r][2], acc[r][3]);
        *(float4*)&Cpart[(size_t)bz * M * N + (size_t)(m0 + ty * 4 + r) * N + n0 + tx * 4] = o;
    }

    if (APART && bx == 0 && tid < 64) {
        float cpart = 0.0f;
#pragma unroll
        for (int kk = 0; kk < 64; kk++)
            cpart += As[tid][kk] * __ldg(&cw[kbeg + kk]);
        atomicAdd(&g_c[m0 + tid], cpart);
    }
}

__device__ __forceinline__ int poprow(unsigned& rem) {
    if (rem == 0) return -1;
    int r = __ffs(rem) - 1;
    rem &= rem - 1;
    return r;
}

// ---------------------------------------------------------------------------
// ONE fused kernel, 1152 blocks.
//  bids 0..127   : setup (q partials -> barrier -> v partials + c), then
//                  signal g_setup_done. All wave-1 resident (lowest bids).
//  bids 128..1151: score tile (b = t>>3, 256 rows). Ballot mask, zero masked
//                  outputs, PRELOAD first 2 rows/warp (DRAM stream starts
//                  immediately, overlapping setup), spin for v-ready, then
//                  dot/tanh/exp with mask-skip + last-block normalize.
// Epoch E = g_launch_cnt / 1152 (exact: 1152 increments per launch, stream-
// ordered between launches). Ready condition: g_setup_done >= (E+1)*128.
// ---------------------------------------------------------------------------
__global__ __launch_bounds__(256, 3) void fused_kernel(
    const float* __restrict__ query, const float* __restrict__ Wq,
    const float* __restrict__ bq, const float* __restrict__ Wk,
    const float* __restrict__ bk,
    const float* __restrict__ target, const int* __restrict__ mask,
    float* __restrict__ out,
    float* __restrict__ part, float* __restrict__ part2,
    int B, int E_dim, int H, int S)
{
    __shared__ float As[64][68];
    __shared__ float Bs[64][68];
    __shared__ unsigned sh_epoch;
    __shared__ bool lastdone;
    int tid = threadIdx.x;
    int bid = blockIdx.x;

    if (tid == 0)
        sh_epoch = g_launch_cnt / GRID_TOTAL;   // stable: < GRID_TOTAL increments in-flight
    __syncthreads();
    unsigned epoch = sh_epoch;

    if (bid < SETUP_BLOCKS) {
        // ----------------- setup path -----------------
        int bx = bid & 7;
        int by = (bid >> 3) & 1;
        int bz = bid >> 4;

        if (bid == 0 && tid < MAX_B) {
            g_c[tid] = 0.0f;
            g_sum[tid] = 0.0f;
            g_cnt[tid] = 0u;
        }

        gemm_tile<1, 0>(query, nullptr, Wq, nullptr, part, B, H, E_dim, bx, by, bz, As, Bs);

        // internal barrier among the 128 setup blocks
        __threadfence();
        __syncthreads();
        if (tid == 0) {
            unsigned t = atomicAdd(&g_bar, 1u);
            unsigned target_ = ((t >> 7) + 1u) << 7;
            while (*(volatile unsigned*)&g_bar < target_) { }
        }
        __syncthreads();
        __threadfence();

        gemm_tile<0, 1>(part, bq, Wk, bk, part2, B, E_dim, H, bx, by, bz, As, Bs);

        // publish: all writes visible, then count this block done
        __threadfence();
        __syncthreads();
        if (tid == 0)
            atomicAdd(&g_setup_done, 1u);
    } else {
        // ----------------- score path -----------------
        int t = bid - SETUP_BLOCKS;
        int b = t >> 3;
        int sblk = (t & 7) * 256;
        int warp = tid >> 5;
        int lane = tid & 31;
        int sbase = sblk + warp * 32;

        const float4* tb = reinterpret_cast<const float4*>(target) +
                           ((size_t)b * S + sbase) * 128;
        const int* mrow = mask + (size_t)b * S;
        float* erow = out + (size_t)b * S;

        // mask ballot; masked rows -> 0 immediately (independent of setup)
        bool keep = (mrow[sbase + lane] != 1);
        unsigned bits = __ballot_sync(0xffffffffu, keep);
        if (!keep) erow[sbase + lane] = 0.0f;

#define LOADROW(buf, r) { const float4* t_ = tb + (size_t)(r) * 128;            \
        buf[0] = __ldcs(t_ + lane);       buf[1] = __ldcs(t_ + lane + 32);      \
        buf[2] = __ldcs(t_ + lane + 64);  buf[3] = __ldcs(t_ + lane + 96); }

#define DOTV(buf, a) { a = buf[0].x * v0.x + buf[0].y * v0.y                    \
                         + buf[0].z * v0.z + buf[0].w * v0.w                    \
                         + buf[1].x * v1.x + buf[1].y * v1.y                    \
                         + buf[1].z * v1.z + buf[1].w * v1.w                    \
                         + buf[2].x * v2.x + buf[2].y * v2.y                    \
                         + buf[2].z * v2.z + buf[2].w * v2.w                    \
                         + buf[3].x * v3.x + buf[3].y * v3.y                    \
                         + buf[3].z * v3.z + buf[3].w * v3.w; }

        // PRELOAD first 2 rows per warp BEFORE waiting: overlaps setup
        unsigned rem = bits;
        float4 c0[4], c1[4], n0[4], n1[4];
        int r0 = poprow(rem);
        int r1 = poprow(rem);
        if (r0 >= 0) LOADROW(c0, r0);
        if (r1 >= 0) LOADROW(c1, r1);

        // wait for setup completion (loads above stay in flight)
        if (tid == 0) {
            unsigned need = (epoch + 1u) * SETUP_BLOCKS;
            while (*(volatile unsigned*)&g_setup_done < need)
                __nanosleep(64);
        }
        __syncthreads();
        __threadfence();

        // v[b] for this lane: sum of 8 split-K partials (L2-hot)
        const int BE4 = MAX_B * MAX_E / 4;
        const float4* vp = reinterpret_cast<const float4*>(part2) + b * 128;
        float4 v0, v1, v2, v3;
#pragma unroll
        for (int j = 0; j < 4; j++) {
            float4 r = __ldg(vp + lane + 32 * j);
#pragma unroll
            for (int p = 1; p < SPLITK; p++) {
                float4 pp = __ldg(vp + p * BE4 + lane + 32 * j);
                r.x += pp.x; r.y += pp.y; r.z += pp.z; r.w += pp.w;
            }
            if (j == 0) v0 = r; else if (j == 1) v1 = r;
            else if (j == 2) v2 = r; else v3 = r;
        }
        float cb = g_c[b];
        float esum = 0.0f;

        while (r0 >= 0) {
            int rn0 = poprow(rem);
            int rn1 = poprow(rem);

            float a0, a1;
            DOTV(c0, a0);
            if (r1 >= 0) { DOTV(c1, a1); } else a1 = 0.0f;

            if (rn0 >= 0) LOADROW(n0, rn0);
            if (rn1 >= 0) LOADROW(n1, rn1);

#pragma unroll
            for (int off = 16; off; off >>= 1) {
                a0 += __shfl_xor_sync(0xffffffffu, a0, off);
                a1 += __shfl_xor_sync(0xffffffffu, a1, off);
            }
            if (lane == 0) {
                float e0 = expf(10.0f * tanhf(a0 + cb) - 10.0f);
                erow[sbase + r0] = e0;
                esum += e0;
                if (r1 >= 0) {
                    float e1 = expf(10.0f * tanhf(a1 + cb) - 10.0f);
                    erow[sbase + r1] = e1;
                    esum += e1;
                }
            }

#pragma unroll
            for (int j = 0; j < 4; j++) { c0[j] = n0[j]; c1[j] = n1[j]; }
            r0 = rn0;
            r1 = rn1;
        }

        if (lane == 0 && esum != 0.0f)
            atomicAdd(&g_sum[b], esum);

        __threadfence();
        __syncthreads();
        if (tid == 0) {
            unsigned c = atomicAdd(&g_cnt[b], 1u);
            lastdone = (c == (unsigned)(S >> 8) - 1u);
        }
        __syncthreads();

        if (lastdone) {
            __threadfence();
            float inv = 1.0f / g_sum[b];
            float4* rowv = reinterpret_cast<float4*>(out + (size_t)b * S);
            for (int i = tid; i < S / 4; i += 256) {
                float4 x = rowv[i];
                x.x *= inv; x.y *= inv; x.z *= inv; x.w *= inv;
                rowv[i] = x;
            }
        }
    }

    // every block, setup or score, retires exactly once per launch
    if (tid == 0)
        atomicAdd(&g_launch_cnt, 1u);
}

// ---------------------------------------------------------------------------
// Inputs (metadata order): query[B,E], target[B,S,E], mask[B,S],
//                          Wq[H,E], bq[H], Wk[H,E], bk[H]
// Output: alpha[B,S] float32
// ---------------------------------------------------------------------------
extern "C" void kernel_launch(void* const* d_in, const int* in_sizes, int n_in,
                              void* d_out, int out_size)
{
    const float* query  = (const float*)d_in[0];
    const float* target = (const float*)d_in[1];
    const int*   mask   = (const int*)d_in[2];
    const float* Wq     = (const float*)d_in[3];
    const float* bq     = (const float*)d_in[4];
    const float* Wk     = (const float*)d_in[5];
    const float* bk     = (const float*)d_in[6];
    float* out = (float*)d_out;

    int H = in_sizes[4];
    int E = in_sizes[1] / in_sizes[2];
    int B = in_sizes[0] / E;
    int S = in_sizes[2] / B;

    float* part_ptr; float* part2_ptr;
    cudaGetSymbolAddress((void**)&part_ptr, g_part);
    cudaGetSymbolAddress((void**)&part2_ptr, g_part2);

    fused_kernel<<<GRID_TOTAL, 256>>>(query, Wq, bq, Wk, bk,
                                      target, mask, out,
                                      part_ptr, part2_ptr, B, E, H, S);
}

// round 15
// speedup vs baseline: 1.2566x; 1.2566x over previous
#include <cuda_runtime.h>
#include <cuda_bf16.h>
#include <math.h>

// Fixed problem shape (from reference): B=128, S=2048, E=512, H=512.
#define MAX_B 128
#define MAX_S 2048
#define MAX_E 512
#define MAX_H 512
#define SPLITK 8

__device__ float g_c[MAX_B];                        // c[b] = q[b].bk
__device__ float g_sum[MAX_B];                      // row sums of exp
__device__ unsigned g_cnt[MAX_B];                   // per-batch completion count
__device__ float g_part[SPLITK * MAX_B * MAX_H];    // q split-K partials
__device__ float g_part2[SPLITK * MAX_B * MAX_E];   // v split-K partials

// ---------------------------------------------------------------------------
// Single-round single-wave split-K GEMM. Block tile 64(M) x 64(N), k-chunk
// = K/SPLITK = 64 loaded in ONE round; grid (N/64, M/64, SPLITK) = 128 blocks
// = one wave. 256 threads, thread tile 4x4 -> 1024 FMA/thread.
// TRANSB=1: C = A @ Bm^T  (Bm [N,K] row-major). Block (0,0,0) zeroes the
//           per-batch accumulators (stream-ordered before gemm2/score).
// TRANSB=0/APART=1: A is a SPLITK-partial array; the 8 partials are summed
//           (+abias) during the A load. blockIdx.x==0 blocks also accumulate
//           c[m] += sum_k q[m,k]*cw[k] into g_c via atomicAdd (tid<64).
// ---------------------------------------------------------------------------
template <int TRANSB, int APART>
__global__ __launch_bounds__(256) void gemm_split_kernel(
    const float* __restrict__ A, const float* __restrict__ abias,
    const float* __restrict__ Bm, const float* __restrict__ cw,
    float* __restrict__ Cpart, int M, int N, int K)
{
    __shared__ float As[64][68];   // 68: float4-aligned, conflict-free
    __shared__ float Bs[64][68];
    int tid = threadIdx.x;
    int m0 = blockIdx.y * 64;
    int n0 = blockIdx.x * 64;
    int kbeg = blockIdx.z * 64;

    if (TRANSB) {  // gemm1: zero per-batch accumulators once
        if (blockIdx.x == 0 && blockIdx.y == 0 && blockIdx.z == 0 && tid < MAX_B) {
            g_c[tid] = 0.0f;
            g_sum[tid] = 0.0f;
            g_cnt[tid] = 0u;
        }
    }

    // ---- A strip: 64 x 64 = 1024 float4, 4 per thread ----
#pragma unroll
    for (int t = 0; t < 4; t++) {
        int idx = tid + t * 256;
        int r = idx >> 4;            // 0..63
        int kq = (idx & 15) * 4;     // 0..60
        size_t off = (size_t)(m0 + r) * K + kbeg + kq;
        float4 a;
        if (APART) {
            int MK = M * K;
            float4 s = *(const float4*)&abias[kbeg + kq];
#pragma unroll
            for (int p = 0; p < SPLITK; p++) {
                float4 pp = *(const float4*)&A[(size_t)p * MK + off];
                s.x += pp.x; s.y += pp.y; s.z += pp.z; s.w += pp.w;
            }
            a = s;
        } else {
            a = *(const float4*)&A[off];
        }
        *(float4*)&As[r][kq] = a;
    }

    // ---- B strip: 64 x 64 = 1024 float4, 4 per thread ----
    if (TRANSB) {
#pragma unroll
        for (int t = 0; t < 4; t++) {
            int idx = tid + t * 256;
            int n = idx >> 4;            // 0..63
            int kq = (idx & 15) * 4;     // 0..60
            float4 v = *(const float4*)&Bm[(size_t)(n0 + n) * K + kbeg + kq];
            Bs[kq][n] = v.x; Bs[kq + 1][n] = v.y; Bs[kq + 2][n] = v.z; Bs[kq + 3][n] = v.w;
        }
    } else {
#pragma unroll
        for (int t = 0; t < 4; t++) {
            int idx = tid + t * 256;
            int kk = idx >> 4;           // 0..63
            int nq = (idx & 15) * 4;     // 0..60
            *(float4*)&Bs[kk][nq] = *(const float4*)&Bm[(size_t)(kbeg + kk) * N + n0 + nq];
        }
    }
    __syncthreads();

    int tx = tid & 15;            // N groups of 4
    int ty = tid >> 4;            // M groups of 4 (0..15)
    float acc[4][4] = {};
#pragma unroll
    for (int kk = 0; kk < 64; kk++) {
        float a0 = As[ty * 4][kk];
        float a1 = As[ty * 4 + 1][kk];
        float a2 = As[ty * 4 + 2][kk];
        float a3 = As[ty * 4 + 3][kk];
        float4 bv = *(const float4*)&Bs[kk][tx * 4];
        acc[0][0] += a0 * bv.x; acc[0][1] += a0 * bv.y; acc[0][2] += a0 * bv.z; acc[0][3] += a0 * bv.w;
        acc[1][0] += a1 * bv.x; acc[1][1] += a1 * bv.y; acc[1][2] += a1 * bv.z; acc[1][3] += a1 * bv.w;
        acc[2][0] += a2 * bv.x; acc[2][1] += a2 * bv.y; acc[2][2] += a2 * bv.z; acc[2][3] += a2 * bv.w;
        acc[3][0] += a3 * bv.x; acc[3][1] += a3 * bv.y; acc[3][2] += a3 * bv.z; acc[3][3] += a3 * bv.w;
    }

#pragma unroll
    for (int r = 0; r < 4; r++) {
        float4 o = make_float4(acc[r][0], acc[r][1], acc[r][2], acc[r][3]);
        *(float4*)&Cpart[(size_t)blockIdx.z * M * N +
                         (size_t)(m0 + ty * 4 + r) * N + n0 + tx * 4] = o;
    }

    if (APART && blockIdx.x == 0 && tid < 64) {
        float cpart = 0.0f;
#pragma unroll
        for (int kk = 0; kk < 64; kk++)
            cpart += As[tid][kk] * __ldg(&cw[kbeg + kk]);
        atomicAdd(&g_c[m0 + tid], cpart);
    }
}

// ---------------------------------------------------------------------------
// Score + softmax with masked-row skipping and block-level load balancing.
// Rows with mask==1 get 0 and their target data is never read. Kept rows are
// compacted into s_list; warps take rows round-robin so counts differ by <=1.
// Last block per batch b normalizes its row. E fixed at 512.
// grid (S/256, B), 256 threads (8 warps).
// ---------------------------------------------------------------------------
__global__ __launch_bounds__(256, 4) void score_kernel(
    const float* __restrict__ target, const int* __restrict__ mask,
    float* __restrict__ out, int S)
{
    __shared__ float4 vsh[128];
    __shared__ unsigned char s_list[256];
    __shared__ int s_wcnt[8];
    __shared__ int s_wbase[9];
    __shared__ bool lastdone;
    int b = blockIdx.y;
    int tid = threadIdx.x;
    int warp = tid >> 5;
    int lane = tid & 31;
    int sblk = blockIdx.x * 256;

    // v[b] reduced from 8 split-K partials into smem
    {
        const int BE4 = MAX_B * MAX_E / 4;
        const float4* vp = reinterpret_cast<const float4*>(&g_part2[0]) + b * 128;
        if (tid < 128) {
            float4 r = vp[tid];
#pragma unroll
            for (int p = 1; p < SPLITK; p++) {
                float4 pp = vp[p * BE4 + tid];
                r.x += pp.x; r.y += pp.y; r.z += pp.z; r.w += pp.w;
            }
            vsh[tid] = r;
        }
    }

    const int* mrow = mask + (size_t)b * S;
    float* erow = out + (size_t)b * S;
    const float4* tb = reinterpret_cast<const float4*>(target) +
                       ((size_t)b * S + sblk) * 128;

    // compact kept rows (thread tid owns row tid of this block)
    bool keep = (mrow[sblk + tid] != 1);
    if (!keep) erow[sblk + tid] = 0.0f;
    unsigned bits = __ballot_sync(0xffffffffu, keep);
    if (lane == 0) s_wcnt[warp] = __popc(bits);
    __syncthreads();
    if (tid == 0) {
        int a = 0;
#pragma unroll
        for (int w = 0; w < 8; w++) { s_wbase[w] = a; a += s_wcnt[w]; }
        s_wbase[8] = a;
    }
    __syncthreads();
    if (keep)
        s_list[s_wbase[warp] + __popc(bits & ((1u << lane) - 1))] = (unsigned char)tid;
    __syncthreads();
    int nk = s_wbase[8];

    float cb = g_c[b];
    float esum = 0.0f;

#define LOADROW(buf, r) { const float4* t_ = tb + (size_t)(r) * 128;            \
        buf[0] = __ldcs(t_ + lane);       buf[1] = __ldcs(t_ + lane + 32);      \
        buf[2] = __ldcs(t_ + lane + 64);  buf[3] = __ldcs(t_ + lane + 96); }

#define DOTV(buf, a) { a = 0.0f;                                                \
        _Pragma("unroll") for (int j_ = 0; j_ < 4; j_++) {                      \
            float4 x_ = buf[j_]; float4 v_ = vsh[lane + 32 * j_];               \
            a += x_.x * v_.x + x_.y * v_.y + x_.z * v_.z + x_.w * v_.w; } }

#define REDUCE_EMIT(a, r) {                                                     \
        _Pragma("unroll") for (int o_ = 16; o_; o_ >>= 1)                       \
            a += __shfl_xor_sync(0xffffffffu, a, o_);                           \
        if (lane == 0) {                                                        \
            float e_ = expf(10.0f * tanhf(a + cb) - 10.0f);                     \
            erow[sblk + (r)] = e_; esum += e_; } }

    {
        float4 bufA[4], bufB[4];
        int rA = (warp < nk) ? (int)s_list[warp] : -1;
        int rB = (warp + 8 < nk) ? (int)s_list[warp + 8] : -1;
        if (rA >= 0) LOADROW(bufA, rA);
        if (rB >= 0) LOADROW(bufB, rB);
        int pn = warp + 16;
        while (rA >= 0) {
            float a;
            DOTV(bufA, a);
            int rn = (pn < nk) ? (int)s_list[pn] : -1; pn += 8;
            if (rn >= 0) LOADROW(bufA, rn);
            REDUCE_EMIT(a, rA);
            rA = rn;
            if (rB < 0) break;
            rn = (pn < nk) ? (int)s_list[pn] : -1; pn += 8;
            DOTV(bufB, a);
            if (rn >= 0) LOADROW(bufB, rn);
            REDUCE_EMIT(a, rB);
            rB = rn;
        }
    }

    if (lane == 0 && esum != 0.0f)
        atomicAdd(&g_sum[b], esum);

    __threadfence();
    __syncthreads();
    if (tid == 0) {
        unsigned t = atomicAdd(&g_cnt[b], 1u);
        lastdone = (t == gridDim.x - 1);
    }
    __syncthreads();

    if (lastdone) {
        __threadfence();
        float inv = 1.0f / g_sum[b];
        float4* rowv = reinterpret_cast<float4*>(out + (size_t)b * S);
        for (int i = tid; i < S / 4; i += 256) {
            float4 x = rowv[i];
            x.x *= inv; x.y *= inv; x.z *= inv; x.w *= inv;
            rowv[i] = x;
        }
    }
}

// ---------------------------------------------------------------------------
// Inputs (metadata order): query[B,E], target[B,S,E], mask[B,S],
//                          Wq[H,E], bq[H], Wk[H,E], bk[H]
// Output: alpha[B,S] float32
// ---------------------------------------------------------------------------
extern "C" void kernel_launch(void* const* d_in, const int* in_sizes, int n_in,
                              void* d_out, int out_size)
{
    const float* query  = (const float*)d_in[0];
    const float* target = (const float*)d_in[1];
    const int*   mask   = (const int*)d_in[2];
    const float* Wq     = (const float*)d_in[3];
    const float* bq     = (const float*)d_in[4];
    const float* Wk     = (const float*)d_in[5];
    const float* bk     = (const float*)d_in[6];
    float* out = (float*)d_out;

    int H = in_sizes[4];
    int E = in_sizes[1] / in_sizes[2];
    int B = in_sizes[0] / E;
    int S = in_sizes[2] / B;

    float* part_ptr; float* part2_ptr;
    cudaGetSymbolAddress((void**)&part_ptr, g_part);
    cudaGetSymbolAddress((void**)&part2_ptr, g_part2);

    // q partials: query @ Wq^T -> g_part  (also zeroes g_c/g_sum/g_cnt)
    {
        dim3 grid(H / 64, B / 64, SPLITK);
        gemm_split_kernel<1, 0><<<grid, 256>>>(query, nullptr, Wq, nullptr,
                                               part_ptr, B, H, E);
    }
    // v partials: (q summed + bq) @ Wk -> g_part2 ; also accumulates c[b]
    {
        dim3 grid(E / 64, B / 64, SPLITK);
        gemm_split_kernel<0, 1><<<grid, 256>>>(part_ptr, bq, Wk, bk,
                                               part2_ptr, B, E, H);
    }
    // fused score + softmax (mask-skip, balanced, last-block normalize)
    {
        dim3 grid(S / 256, B);
        score_kernel<<<grid, 256>>>(target, mask, out, S);
    }
}

// round 16
// speedup vs baseline: 1.3002x; 1.0347x over previous
#include <cuda_runtime.h>
#include <cuda_bf16.h>
#include <math.h>

// Fixed problem shape (from reference): B=128, S=2048, E=512, H=512.
#define MAX_B 128
#define MAX_S 2048
#define MAX_E 512
#define MAX_H 512
#define SPLITK 8

__device__ float g_c[MAX_B];                        // c[b] = q[b].bk
__device__ float g_sum[MAX_B];                      // row sums of exp
__device__ unsigned g_cnt[MAX_B];                   // per-batch completion count
__device__ float g_part[SPLITK * MAX_B * MAX_H];    // q split-K partials
__device__ float g_part2[SPLITK * MAX_B * MAX_E];   // v split-K partials

// ---------------------------------------------------------------------------
// Single-round single-wave split-K GEMM (R7-proven), PDL-enabled.
// Block tile 64x64, k-chunk 64 in ONE round; grid = 128 blocks = one wave.
// TRANSB=1 (gemm1): C = A @ Bm^T. Triggers PDL completion at entry so gemm2
//           can launch concurrently. Block (0,0,0) zeroes accumulators.
// TRANSB=0/APART=1 (gemm2): loads the INDEPENDENT B strip (Wk) first, then
//           cudaGridDependencySynchronize() before reading g_part (gemm1
//           output). Also triggers at entry so score can launch early.
//           blockIdx.x==0 accumulates c[m] into g_c (tid<64).
// ---------------------------------------------------------------------------
template <int TRANSB, int APART>
__global__ __launch_bounds__(256) void gemm_split_kernel(
    const float* __restrict__ A, const float* __restrict__ abias,
    const float* __restrict__ Bm, const float* __restrict__ cw,
    float* __restrict__ Cpart, int M, int N, int K)
{
    __shared__ float As[64][68];   // 68: float4-aligned, conflict-free
    __shared__ float Bs[64][68];
    int tid = threadIdx.x;
    int m0 = blockIdx.y * 64;
    int n0 = blockIdx.x * 64;
    int kbeg = blockIdx.z * 64;

#if __CUDA_ARCH__ >= 900
    cudaTriggerProgrammaticLaunchCompletion();   // let dependent kernel launch
#endif

    if (TRANSB) {  // gemm1: zero per-batch accumulators once
        if (blockIdx.x == 0 && blockIdx.y == 0 && blockIdx.z == 0 && tid < MAX_B) {
            g_c[tid] = 0.0f;
            g_sum[tid] = 0.0f;
            g_cnt[tid] = 0u;
        }
    }

    // ---- B strip first (independent of upstream kernel) ----
    if (TRANSB) {
#pragma unroll
        for (int t = 0; t < 4; t++) {
            int idx = tid + t * 256;
            int n = idx >> 4;            // 0..63
            int kq = (idx & 15) * 4;     // 0..60
            float4 v = *(const float4*)&Bm[(size_t)(n0 + n) * K + kbeg + kq];
            Bs[kq][n] = v.x; Bs[kq + 1][n] = v.y; Bs[kq + 2][n] = v.z; Bs[kq + 3][n] = v.w;
        }
    } else {
#pragma unroll
        for (int t = 0; t < 4; t++) {
            int idx = tid + t * 256;
            int kk = idx >> 4;           // 0..63
            int nq = (idx & 15) * 4;     // 0..60
            *(float4*)&Bs[kk][nq] = *(const float4*)&Bm[(size_t)(kbeg + kk) * N + n0 + nq];
        }
    }

#if __CUDA_ARCH__ >= 900
    if (APART)
        cudaGridDependencySynchronize();         // g_part must be complete
#endif

    // ---- A strip: 64 x 64 = 1024 float4, 4 per thread ----
#pragma unroll
    for (int t = 0; t < 4; t++) {
        int idx = tid + t * 256;
        int r = idx >> 4;            // 0..63
        int kq = (idx & 15) * 4;     // 0..60
        size_t off = (size_t)(m0 + r) * K + kbeg + kq;
        float4 a;
        if (APART) {
            int MK = M * K;
            float4 s = *(const float4*)&abias[kbeg + kq];
#pragma unroll
            for (int p = 0; p < SPLITK; p++) {
                float4 pp = *(const float4*)&A[(size_t)p * MK + off];
                s.x += pp.x; s.y += pp.y; s.z += pp.z; s.w += pp.w;
            }
            a = s;
        } else {
            a = *(const float4*)&A[off];
        }
        *(float4*)&As[r][kq] = a;
    }
    __syncthreads();

    int tx = tid & 15;            // N groups of 4
    int ty = tid >> 4;            // M groups of 4 (0..15)
    float acc[4][4] = {};
#pragma unroll
    for (int kk = 0; kk < 64; kk++) {
        float a0 = As[ty * 4][kk];
        float a1 = As[ty * 4 + 1][kk];
        float a2 = As[ty * 4 + 2][kk];
        float a3 = As[ty * 4 + 3][kk];
        float4 bv = *(const float4*)&Bs[kk][tx * 4];
        acc[0][0] += a0 * bv.x; acc[0][1] += a0 * bv.y; acc[0][2] += a0 * bv.z; acc[0][3] += a0 * bv.w;
        acc[1][0] += a1 * bv.x; acc[1][1] += a1 * bv.y; acc[1][2] += a1 * bv.z; acc[1][3] += a1 * bv.w;
        acc[2][0] += a2 * bv.x; acc[2][1] += a2 * bv.y; acc[2][2] += a2 * bv.z; acc[2][3] += a2 * bv.w;
        acc[3][0] += a3 * bv.x; acc[3][1] += a3 * bv.y; acc[3][2] += a3 * bv.z; acc[3][3] += a3 * bv.w;
    }

#pragma unroll
    for (int r = 0; r < 4; r++) {
        float4 o = make_float4(acc[r][0], acc[r][1], acc[r][2], acc[r][3]);
        *(float4*)&Cpart[(size_t)blockIdx.z * M * N +
                         (size_t)(m0 + ty * 4 + r) * N + n0 + tx * 4] = o;
    }

    if (APART && blockIdx.x == 0 && tid < 64) {
        float cpart = 0.0f;
#pragma unroll
        for (int kk = 0; kk < 64; kk++)
            cpart += As[tid][kk] * __ldg(&cw[kbeg + kk]);
        atomicAdd(&g_c[m0 + tid], cpart);
    }
}

// ---------------------------------------------------------------------------
// Score + softmax (R7-proven balanced variant), PDL-enabled.
// Prologue (mask ballot, compaction, zeroing masked outputs, FIRST target
// row loads) is independent of setup and runs before
// cudaGridDependencySynchronize(); the v-reduction and dot loop follow.
// Rows with mask==1 get 0 and their target data is never read.
// Last block per batch b normalizes its row. E fixed at 512.
// grid (S/256, B), 256 threads (8 warps).
// ---------------------------------------------------------------------------
__global__ __launch_bounds__(256, 4) void score_kernel(
    const float* __restrict__ target, const int* __restrict__ mask,
    float* __restrict__ out, int S)
{
    __shared__ float4 vsh[128];
    __shared__ unsigned char s_list[256];
    __shared__ int s_wcnt[8];
    __shared__ int s_wbase[9];
    __shared__ bool lastdone;
    int b = blockIdx.y;
    int tid = threadIdx.x;
    int warp = tid >> 5;
    int lane = tid & 31;
    int sblk = blockIdx.x * 256;

    const int* mrow = mask + (size_t)b * S;
    float* erow = out + (size_t)b * S;
    const float4* tb = reinterpret_cast<const float4*>(target) +
                       ((size_t)b * S + sblk) * 128;

    // ---- prologue: independent of setup ----
    bool keep = (mrow[sblk + tid] != 1);
    if (!keep) erow[sblk + tid] = 0.0f;
    unsigned bits = __ballot_sync(0xffffffffu, keep);
    if (lane == 0) s_wcnt[warp] = __popc(bits);
    __syncthreads();
    if (tid == 0) {
        int a = 0;
#pragma unroll
        for (int w = 0; w < 8; w++) { s_wbase[w] = a; a += s_wcnt[w]; }
        s_wbase[8] = a;
    }
    __syncthreads();
    if (keep)
        s_list[s_wbase[warp] + __popc(bits & ((1u << lane) - 1))] = (unsigned char)tid;
    __syncthreads();
    int nk = s_wbase[8];

#define LOADROW(buf, r) { const float4* t_ = tb + (size_t)(r) * 128;            \
        buf[0] = __ldcs(t_ + lane);       buf[1] = __ldcs(t_ + lane + 32);      \
        buf[2] = __ldcs(t_ + lane + 64);  buf[3] = __ldcs(t_ + lane + 96); }

#define DOTV(buf, a) { a = 0.0f;                                                \
        _Pragma("unroll") for (int j_ = 0; j_ < 4; j_++) {                      \
            float4 x_ = buf[j_]; float4 v_ = vsh[lane + 32 * j_];               \
            a += x_.x * v_.x + x_.y * v_.y + x_.z * v_.z + x_.w * v_.w; } }

#define REDUCE_EMIT(a, r) {                                                     \
        _Pragma("unroll") for (int o_ = 16; o_; o_ >>= 1)                       \
            a += __shfl_xor_sync(0xffffffffu, a, o_);                           \
        if (lane == 0) {                                                        \
            float e_ = expf(10.0f * tanhf(a + cb) - 10.0f);                     \
            erow[sblk + (r)] = e_; esum += e_; } }

    // first two rows per warp: issue loads BEFORE waiting on setup
    float4 bufA[4], bufB[4];
    int rA = (warp < nk) ? (int)s_list[warp] : -1;
    int rB = (warp + 8 < nk) ? (int)s_list[warp + 8] : -1;
    if (rA >= 0) LOADROW(bufA, rA);
    if (rB >= 0) LOADROW(bufB, rB);

#if __CUDA_ARCH__ >= 900
    cudaGridDependencySynchronize();             // setup outputs must be ready
#endif

    // v[b] reduced from 8 split-K partials into smem (L2-hot)
    {
        const int BE4 = MAX_B * MAX_E / 4;
        const float4* vp = reinterpret_cast<const float4*>(&g_part2[0]) + b * 128;
        if (tid < 128) {
            float4 r = vp[tid];
#pragma unroll
            for (int p = 1; p < SPLITK; p++) {
                float4 pp = vp[p * BE4 + tid];
                r.x += pp.x; r.y += pp.y; r.z += pp.z; r.w += pp.w;
            }
            vsh[tid] = r;
        }
    }
    __syncthreads();

    float cb = g_c[b];
    float esum = 0.0f;

    {
        int pn = warp + 16;
        while (rA >= 0) {
            float a;
            DOTV(bufA, a);
            int rn = (pn < nk) ? (int)s_list[pn] : -1; pn += 8;
            if (rn >= 0) LOADROW(bufA, rn);
            REDUCE_EMIT(a, rA);
            rA = rn;
            if (rB < 0) break;
            rn = (pn < nk) ? (int)s_list[pn] : -1; pn += 8;
            DOTV(bufB, a);
            if (rn >= 0) LOADROW(bufB, rn);
            REDUCE_EMIT(a, rB);
            rB = rn;
        }
    }

    if (lane == 0 && esum != 0.0f)
        atomicAdd(&g_sum[b], esum);

    __threadfence();
    __syncthreads();
    if (tid == 0) {
        unsigned t = atomicAdd(&g_cnt[b], 1u);
        lastdone = (t == gridDim.x - 1);
    }
    __syncthreads();

    if (lastdone) {
        __threadfence();
        float inv = 1.0f / g_sum[b];
        float4* rowv = reinterpret_cast<float4*>(out + (size_t)b * S);
        for (int i = tid; i < S / 4; i += 256) {
            float4 x = rowv[i];
            x.x *= inv; x.y *= inv; x.z *= inv; x.w *= inv;
            rowv[i] = x;
        }
    }
}

// ---------------------------------------------------------------------------
// Inputs (metadata order): query[B,E], target[B,S,E], mask[B,S],
//                          Wq[H,E], bq[H], Wk[H,E], bk[H]
// Output: alpha[B,S] float32
// ---------------------------------------------------------------------------
extern "C" void kernel_launch(void* const* d_in, const int* in_sizes, int n_in,
                              void* d_out, int out_size)
{
    const float* query  = (const float*)d_in[0];
    const float* target = (const float*)d_in[1];
    const int*   mask   = (const int*)d_in[2];
    const float* Wq     = (const float*)d_in[3];
    const float* bq     = (const float*)d_in[4];
    const float* Wk     = (const float*)d_in[5];
    const float* bk     = (const float*)d_in[6];
    float* out = (float*)d_out;

    int H = in_sizes[4];
    int E = in_sizes[1] / in_sizes[2];
    int B = in_sizes[0] / E;
    int S = in_sizes[2] / B;

    float* part_ptr; float* part2_ptr;
    cudaGetSymbolAddress((void**)&part_ptr, g_part);
    cudaGetSymbolAddress((void**)&part2_ptr, g_part2);

    cudaLaunchAttribute pdl[1];
    pdl[0].id = cudaLaunchAttributeProgrammaticStreamSerialization;
    pdl[0].val.programmaticStreamSerializationAllowed = 1;

    // gemm1: q partials (normal launch; triggers PDL for gemm2)
    {
        dim3 grid(H / 64, B / 64, SPLITK);
        gemm_split_kernel<1, 0><<<grid, 256>>>(query, nullptr, Wq, nullptr,
                                               part_ptr, B, H, E);
    }
    // gemm2: v partials + c, PDL — overlaps Wk load with gemm1
    {
        cudaLaunchConfig_t cfg = {};
        cfg.gridDim = dim3(E / 64, B / 64, SPLITK);
        cfg.blockDim = dim3(256);
        cfg.stream = 0;
        cfg.attrs = pdl;
        cfg.numAttrs = 1;
        cudaLaunchKernelEx(&cfg, gemm_split_kernel<0, 1>,
                           (const float*)part_ptr, bq, Wk, bk,
                           part2_ptr, B, E, H);
    }
    // score: PDL — overlaps mask ballot + first target loads with setup
    {
        cudaLaunchConfig_t cfg = {};
        cfg.gridDim = dim3(S / 256, B);
        cfg.blockDim = dim3(256);
        cfg.stream = 0;
        cfg.attrs = pdl;
        cfg.numAttrs = 1;
        cudaLaunchKernelEx(&cfg, score_kernel, target, mask, out, S);
    }
}

// round 17
// speedup vs baseline: 1.3440x; 1.0337x over previous
#include <cuda_runtime.h>
#include <cuda_bf16.h>
#include <math.h>

// Fixed problem shape (from reference): B=128, S=2048, E=512, H=512.
#define MAX_B 128
#define MAX_S 2048
#define MAX_E 512
#define MAX_H 512
#define SPLITK 8

__device__ float g_c[MAX_B];                        // c[b] = q[b].bk
__device__ float g_sum[MAX_B];                      // row sums of exp
__device__ unsigned g_cnt[MAX_B];                   // per-batch completion count
__device__ float g_part[SPLITK * MAX_B * MAX_H];    // q split-K partials
__device__ float g_part2[SPLITK * MAX_B * MAX_E];   // v split-K partials

// ---------------------------------------------------------------------------
// Single-round single-wave split-K GEMM (R7-proven), PDL-enabled.
// Block tile 64x64, k-chunk 64 in ONE round; grid = 128 blocks = one wave.
// TRANSB=1 (gemm1): C = A @ Bm^T. Triggers PDL completion at entry so gemm2
//           can launch concurrently. Block (0,0,0) zeroes accumulators.
// TRANSB=0/APART=1 (gemm2): loads the INDEPENDENT B strip (Wk) first, then
//           cudaGridDependencySynchronize() before reading g_part (gemm1
//           output). Also triggers at entry so score can launch early.
//           blockIdx.x==0 accumulates c[m] into g_c (tid<64).
// ---------------------------------------------------------------------------
template <int TRANSB, int APART>
__global__ __launch_bounds__(256) void gemm_split_kernel(
    const float* __restrict__ A, const float* __restrict__ abias,
    const float* __restrict__ Bm, const float* __restrict__ cw,
    float* __restrict__ Cpart, int M, int N, int K)
{
    __shared__ float As[64][68];   // 68: float4-aligned, conflict-free
    __shared__ float Bs[64][68];
    int tid = threadIdx.x;
    int m0 = blockIdx.y * 64;
    int n0 = blockIdx.x * 64;
    int kbeg = blockIdx.z * 64;

#if __CUDA_ARCH__ >= 900
    cudaTriggerProgrammaticLaunchCompletion();   // let dependent kernel launch
#endif

    if (TRANSB) {  // gemm1: zero per-batch accumulators once
        if (blockIdx.x == 0 && blockIdx.y == 0 && blockIdx.z == 0 && tid < MAX_B) {
            g_c[tid] = 0.0f;
            g_sum[tid] = 0.0f;
            g_cnt[tid] = 0u;
        }
    }

    // ---- B strip first (independent of upstream kernel) ----
    if (TRANSB) {
#pragma unroll
        for (int t = 0; t < 4; t++) {
            int idx = tid + t * 256;
            int n = idx >> 4;            // 0..63
            int kq = (idx & 15) * 4;     // 0..60
            float4 v = *(const float4*)&Bm[(size_t)(n0 + n) * K + kbeg + kq];
            Bs[kq][n] = v.x; Bs[kq + 1][n] = v.y; Bs[kq + 2][n] = v.z; Bs[kq + 3][n] = v.w;
        }
    } else {
#pragma unroll
        for (int t = 0; t < 4; t++) {
            int idx = tid + t * 256;
            int kk = idx >> 4;           // 0..63
            int nq = (idx & 15) * 4;     // 0..60
            *(float4*)&Bs[kk][nq] = *(const float4*)&Bm[(size_t)(kbeg + kk) * N + n0 + nq];
        }
    }

#if __CUDA_ARCH__ >= 900
    if (APART)
        cudaGridDependencySynchronize();         // g_part must be complete
#endif

    // ---- A strip: 64 x 64 = 1024 float4, 4 per thread ----
#pragma unroll
    for (int t = 0; t < 4; t++) {
        int idx = tid + t * 256;
        int r = idx >> 4;            // 0..63
        int kq = (idx & 15) * 4;     // 0..60
        size_t off = (size_t)(m0 + r) * K + kbeg + kq;
        float4 a;
        if (APART) {
            int MK = M * K;
            float4 s = *(const float4*)&abias[kbeg + kq];
#pragma unroll
            for (int p = 0; p < SPLITK; p++) {
                float4 pp = *(const float4*)&A[(size_t)p * MK + off];
                s.x += pp.x; s.y += pp.y; s.z += pp.z; s.w += pp.w;
            }
            a = s;
        } else {
            a = *(const float4*)&A[off];
        }
        *(float4*)&As[r][kq] = a;
    }
    __syncthreads();

    int tx = tid & 15;            // N groups of 4
    int ty = tid >> 4;            // M groups of 4 (0..15)
    float acc[4][4] = {};
#pragma unroll
    for (int kk = 0; kk < 64; kk++) {
        float a0 = As[ty * 4][kk];
        float a1 = As[ty * 4 + 1][kk];
        float a2 = As[ty * 4 + 2][kk];
        float a3 = As[ty * 4 + 3][kk];
        float4 bv = *(const float4*)&Bs[kk][tx * 4];
        acc[0][0] += a0 * bv.x; acc[0][1] += a0 * bv.y; acc[0][2] += a0 * bv.z; acc[0][3] += a0 * bv.w;
        acc[1][0] += a1 * bv.x; acc[1][1] += a1 * bv.y; acc[1][2] += a1 * bv.z; acc[1][3] += a1 * bv.w;
        acc[2][0] += a2 * bv.x; acc[2][1] += a2 * bv.y; acc[2][2] += a2 * bv.z; acc[2][3] += a2 * bv.w;
        acc[3][0] += a3 * bv.x; acc[3][1] += a3 * bv.y; acc[3][2] += a3 * bv.z; acc[3][3] += a3 * bv.w;
    }

#pragma unroll
    for (int r = 0; r < 4; r++) {
        float4 o = make_float4(acc[r][0], acc[r][1], acc[r][2], acc[r][3]);
        *(float4*)&Cpart[(size_t)blockIdx.z * M * N +
                         (size_t)(m0 + ty * 4 + r) * N + n0 + tx * 4] = o;
    }

    if (APART && blockIdx.x == 0 && tid < 64) {
        float cpart = 0.0f;
#pragma unroll
        for (int kk = 0; kk < 64; kk++)
            cpart += As[tid][kk] * __ldg(&cw[kbeg + kk]);
        atomicAdd(&g_c[m0 + tid], cpart);
    }
}

// ---------------------------------------------------------------------------
// Score + softmax (R7-proven balanced variant), PDL + deep L2 prefetch.
// Prologue (mask ballot, compaction, zeroing masked outputs) is independent
// of setup; each warp then issues register-free prefetch.global.L2 for ALL
// its kept rows (one instr covers a 512B row: 32 lanes x 16B) and loads the
// first two rows, all BEFORE cudaGridDependencySynchronize(). This saturates
// the otherwise-idle DRAM bus during the setup window.
// Rows with mask==1 get 0 and their target data is never read.
// Last block per batch b normalizes its row. E fixed at 512.
// grid (S/256, B), 256 threads (8 warps).
// ---------------------------------------------------------------------------
__global__ __launch_bounds__(256, 4) void score_kernel(
    const float* __restrict__ target, const int* __restrict__ mask,
    float* __restrict__ out, int S)
{
    __shared__ float4 vsh[128];
    __shared__ unsigned char s_list[256];
    __shared__ int s_wcnt[8];
    __shared__ int s_wbase[9];
    __shared__ bool lastdone;
    int b = blockIdx.y;
    int tid = threadIdx.x;
    int warp = tid >> 5;
    int lane = tid & 31;
    int sblk = blockIdx.x * 256;

    const int* mrow = mask + (size_t)b * S;
    float* erow = out + (size_t)b * S;
    const float4* tb = reinterpret_cast<const float4*>(target) +
                       ((size_t)b * S + sblk) * 128;

    // ---- prologue: independent of setup ----
    bool keep = (mrow[sblk + tid] != 1);
    if (!keep) erow[sblk + tid] = 0.0f;
    unsigned bits = __ballot_sync(0xffffffffu, keep);
    if (lane == 0) s_wcnt[warp] = __popc(bits);
    __syncthreads();
    if (tid == 0) {
        int a = 0;
#pragma unroll
        for (int w = 0; w < 8; w++) { s_wbase[w] = a; a += s_wcnt[w]; }
        s_wbase[8] = a;
    }
    __syncthreads();
    if (keep)
        s_list[s_wbase[warp] + __popc(bits & ((1u << lane) - 1))] = (unsigned char)tid;
    __syncthreads();
    int nk = s_wbase[8];

    // deep L2 prefetch of ALL this warp's kept rows (fire-and-forget).
    // One warp instruction covers a full 512B row (32 lanes x 16B).
    for (int p = warp; p < nk; p += 8) {
        int r = (int)s_list[p];
        const char* a_ = (const char*)(tb + (size_t)r * 128) + lane * 16;
        asm volatile("prefetch.global.L2 [%0];" :: "l"(a_));
    }

#define LOADROW(buf, r) { const float4* t_ = tb + (size_t)(r) * 128;            \
        buf[0] = __ldcs(t_ + lane);       buf[1] = __ldcs(t_ + lane + 32);      \
        buf[2] = __ldcs(t_ + lane + 64);  buf[3] = __ldcs(t_ + lane + 96); }

#define DOTV(buf, a) { a = 0.0f;                                                \
        _Pragma("unroll") for (int j_ = 0; j_ < 4; j_++) {                      \
            float4 x_ = buf[j_]; float4 v_ = vsh[lane + 32 * j_];               \
            a += x_.x * v_.x + x_.y * v_.y + x_.z * v_.z + x_.w * v_.w; } }

#define REDUCE_EMIT(a, r) {                                                     \
        _Pragma("unroll") for (int o_ = 16; o_; o_ >>= 1)                       \
            a += __shfl_xor_sync(0xffffffffu, a, o_);                           \
        if (lane == 0) {                                                        \
            float e_ = expf(10.0f * tanhf(a + cb) - 10.0f);                     \
            erow[sblk + (r)] = e_; esum += e_; } }

    // first two rows per warp: issue loads BEFORE waiting on setup
    float4 bufA[4], bufB[4];
    int rA = (warp < nk) ? (int)s_list[warp] : -1;
    int rB = (warp + 8 < nk) ? (int)s_list[warp + 8] : -1;
    if (rA >= 0) LOADROW(bufA, rA);
    if (rB >= 0) LOADROW(bufB, rB);

#if __CUDA_ARCH__ >= 900
    cudaGridDependencySynchronize();             // setup outputs must be ready
#endif

    // v[b] reduced from 8 split-K partials into smem (L2-hot)
    {
        const int BE4 = MAX_B * MAX_E / 4;
        const float4* vp = reinterpret_cast<const float4*>(&g_part2[0]) + b * 128;
        if (tid < 128) {
            float4 r = vp[tid];
#pragma unroll
            for (int p = 1; p < SPLITK; p++) {
                float4 pp = vp[p * BE4 + tid];
                r.x += pp.x; r.y += pp.y; r.z += pp.z; r.w += pp.w;
            }
            vsh[tid] = r;
        }
    }
    __syncthreads();

    float cb = g_c[b];
    float esum = 0.0f;

    {
        int pn = warp + 16;
        while (rA >= 0) {
            float a;
            DOTV(bufA, a);
            int rn = (pn < nk) ? (int)s_list[pn] : -1; pn += 8;
            if (rn >= 0) LOADROW(bufA, rn);
            REDUCE_EMIT(a, rA);
            rA = rn;
            if (rB < 0) break;
            rn = (pn < nk) ? (int)s_list[pn] : -1; pn += 8;
            DOTV(bufB, a);
            if (rn >= 0) LOADROW(bufB, rn);
            REDUCE_EMIT(a, rB);
            rB = rn;
        }
    }

    if (lane == 0 && esum != 0.0f)
        atomicAdd(&g_sum[b], esum);

    __threadfence();
    __syncthreads();
    if (tid == 0) {
        unsigned t = atomicAdd(&g_cnt[b], 1u);
        lastdone = (t == gridDim.x - 1);
    }
    __syncthreads();

    if (lastdone) {
        __threadfence();
        float inv = 1.0f / g_sum[b];
        float4* rowv = reinterpret_cast<float4*>(out + (size_t)b * S);
        for (int i = tid; i < S / 4; i += 256) {
            float4 x = rowv[i];
            x.x *= inv; x.y *= inv; x.z *= inv; x.w *= inv;
            rowv[i] = x;
        }
    }
}

// ---------------------------------------------------------------------------
// Inputs (metadata order): query[B,E], target[B,S,E], mask[B,S],
//                          Wq[H,E], bq[H], Wk[H,E], bk[H]
// Output: alpha[B,S] float32
// ---------------------------------------------------------------------------
extern "C" void kernel_launch(void* const* d_in, const int* in_sizes, int n_in,
                              void* d_out, int out_size)
{
    const float* query  = (const float*)d_in[0];
    const float* target = (const float*)d_in[1];
    const int*   mask   = (const int*)d_in[2];
    const float* Wq     = (const float*)d_in[3];
    const float* bq     = (const float*)d_in[4];
    const float* Wk     = (const float*)d_in[5];
    const float* bk     = (const float*)d_in[6];
    float* out = (float*)d_out;

    int H = in_sizes[4];
    int E = in_sizes[1] / in_sizes[2];
    int B = in_sizes[0] / E;
    int S = in_sizes[2] / B;

    float* part_ptr; float* part2_ptr;
    cudaGetSymbolAddress((void**)&part_ptr, g_part);
    cudaGetSymbolAddress((void**)&part2_ptr, g_part2);

    cudaLaunchAttribute pdl[1];
    pdl[0].id = cudaLaunchAttributeProgrammaticStreamSerialization;
    pdl[0].val.programmaticStreamSerializationAllowed = 1;

    // gemm1: q partials (normal launch; triggers PDL for gemm2)
    {
        dim3 grid(H / 64, B / 64, SPLITK);
        gemm_split_kernel<1, 0><<<grid, 256>>>(query, nullptr, Wq, nullptr,
                                               part_ptr, B, H, E);
    }
    // gemm2: v partials + c, PDL — overlaps Wk load with gemm1
    {
        cudaLaunchConfig_t cfg = {};
        cfg.gridDim = dim3(E / 64, B / 64, SPLITK);
        cfg.blockDim = dim3(256);
        cfg.stream = 0;
        cfg.attrs = pdl;
        cfg.numAttrs = 1;
        cudaLaunchKernelEx(&cfg, gemm_split_kernel<0, 1>,
                           (const float*)part_ptr, bq, Wk, bk,
                           part2_ptr, B, E, H);
    }
    // score: PDL — mask ballot + deep L2 prefetch + first loads overlap setup
    {
        cudaLaunchConfig_t cfg = {};
        cfg.gridDim = dim3(S / 256, B);
        cfg.blockDim = dim3(256);
        cfg.stream = 0;
        cfg.attrs = pdl;
        cfg.numAttrs = 1;
        cudaLaunchKernelEx(&cfg, score_kernel, target, mask, out, S);
    }
}